// round 15
// baseline (speedup 1.0000x reference)
#include <cuda_runtime.h>

#define BB 64
#define TT 1024
#define NN 48
#define CH 8
#define PF 3   // 1023 steps = 341 * 3 exactly -> no tail guard, branch-free body
#define NBLK (BB + BB * CH)   // 64 chains + 512 scores = 576 blocks
#define NTH 192               // 4-way i-split: p = tid & 3, j = tid >> 2

// Scratch (no cudaMalloc allowed)
__device__ float g_lognorm[BB];
__device__ float g_part[BB][CH];
__device__ int   g_count = 0;   // combine ticket; reset by combiner each call

__global__ __launch_bounds__(NTH) void crf_main(
    const float* __restrict__ y_true,
    const float* __restrict__ y_pred,
    const int*   __restrict__ spk,
    const float* __restrict__ tr0,
    const float* __restrict__ tr1,
    const float* __restrict__ tr2,
    float* __restrict__ out)
{
    // Chain: Esh (3 x 48 x 48, row stride 50, conflict-free scalar loads)
    // + vsh[2][2][48] (A/B half-partials, double buffered). Scores overlay.
    __shared__ __align__(16) float sbuf[3 * 2400 + 192];
    __shared__ int s_last;
    const int tid = threadIdx.x;
    const int p = tid & 3;        // i-quarter: rows 12p .. 12p+11
    const int j = tid >> 2;       // output column 0..47

    if (blockIdx.x < BB) {
        // ================= Forward recursion: one block per batch =================
        const int b = blockIdx.x;
        float* Esh = sbuf;              // exp(TRANS), k stride 2400, row stride 50
        float* vsh = sbuf + 7200;       // [buf][half][48]

        for (int idx = tid; idx < 3 * 48 * 48; idx += NTH) {
            int k  = idx / 2304;
            int rc = idx - k * 2304;
            int r  = rc / 48;
            int cc = rc - r * 48;
            const float* Tk = (k == 0) ? tr0 : (k == 1) ? tr1 : tr2;
            Esh[k * 2400 + r * 50 + cc] = __expf(Tk[rc]);
        }

        const float* ypb = y_pred + b * TT * NN;
        const int*   spb = spk + b * (TT - 1);

        // v_0 = exp(state_0) in A-half, zeros in B-half.
        if (tid < 48) {
            vsh[tid]      = __expf(ypb[tid]);
            vsh[48 + tid] = 0.f;
        }

        // Register prefetch ring for emissions + transition selectors.
        float ebuf[PF];
        int   kbuf[PF];
        #pragma unroll
        for (int u = 0; u < PF; u++) {
            ebuf[u] = ypb[(1 + u) * NN + j];
            kbuf[u] = spb[u];
        }
        __syncthreads();

        float m = 0.f;
        float prod = 1.f;                  // lazy renorm-log accumulator
        int cur = 0;
        int t = 1;
        for (int blk = 0; blk < (TT - 1) / PF; blk++) {   // 341 iterations, no tail
            #pragma unroll
            for (int u = 0; u < PF; u++) {
                const int   kk   = kbuf[u];
                const float emit = ebuf[u];
                // Prefetch PF steps ahead (branch-free clamp).
                int tpc  = min(t + PF, TT - 1);
                int sidx = min(t + PF - 1, TT - 2);
                ebuf[u] = ypb[tpc * NN + j];
                kbuf[u] = spb[sidx];

                const float* A  = vsh + cur * 96;   // half-partial arrays
                const float* Bv = A + 48;

                // Renorm factor: broadcast scalars + MUFU, parallel with the dot.
                float v00 = A[0] + Bv[0];
                float pe  = __expf(emit);
                float rp  = __fdividef(pe, v00);

                // E column slice for this (kk, j, quarter p): 12 scalar loads,
                // bank = (24p + 18i + j) mod 32 -> all 32 distinct per phase.
                const float* Ekj = Esh + kk * 2400 + (12 * p) * 50 + j;

                // Combined state slice (3x two broadcast float4 reads + FADD)
                // then 12-term quarter dot, 3 accumulators.
                float a0 = 0.f, a1 = 0.f, a2 = 0.f;
                #pragma unroll
                for (int q = 0; q < 3; q++) {
                    float4 x4 = *(const float4*)(A  + 12 * p + 4 * q);
                    float4 y4 = *(const float4*)(Bv + 12 * p + 4 * q);
                    a0 += (x4.x + y4.x) * Ekj[(4 * q    ) * 50];
                    a1 += (x4.y + y4.y) * Ekj[(4 * q + 1) * 50];
                    a2 += (x4.z + y4.z) * Ekj[(4 * q + 2) * 50];
                    a0 += (x4.w + y4.w) * Ekj[(4 * q + 3) * 50];
                }
                float quarter = a0 + (a1 + a2);
                // One shfl: quarters (0,1) -> half A partial, (2,3) -> half B.
                float half = quarter + __shfl_xor_sync(0xffffffffu, quarter, 1);

                // Threads p = 0 store half A, p = 2 store half B (rp folded in).
                if ((p & 1) == 0)
                    vsh[(cur ^ 1) * 96 + (p >> 1) * 48 + j] = half * rp;
                if (tid == 0) {
                    prod *= v00;                   // lazy: flush log once per blk
                    if (u == PF - 1) { m += __logf(prod); prod = 1.f; }
                }
                __syncthreads();
                cur ^= 1;
                t++;
            }
        }
        if (tid == 0) {
            const float* A = vsh + cur * 96;
            float ssum = 0.f;
            for (int q = 0; q < 48; q++) ssum += A[q] + A[48 + q];  // fixed order
            g_lognorm[b] = m + __logf(ssum);
        }
    } else {
        // ================= Score reductions: (b, chunk) blocks =================
        int idx = blockIdx.x - BB;
        int b   = idx / CH;
        int c   = idx - b * CH;

        float* l1sh = sbuf;        // [2][48] double buffer
        float* red  = sbuf + 96;   // NTH-wide reduction scratch

        // Per-thread register copies of raw TRANS: column j, rows 12p..12p+11.
        float T0[12], T1[12], T2[12];
        #pragma unroll
        for (int i = 0; i < 12; i++) {
            int rc = (12 * p + i) * NN + j;
            T0[i] = tr0[rc];
            T1[i] = tr1[rc];
            T2[i] = tr2[rc];
        }

        const float* ytb = y_true + b * TT * NN;
        const float* ypb = y_pred + b * TT * NN;
        const int*   spb = spk + b * (TT - 1);

        const int LEN = (TT - 1 + CH - 1) / CH;   // 128
        int tA  = c * LEN;
        int tBn = tA + LEN; if (tBn > TT - 1) tBn = TT - 1;

        float pacc = 0.f, tacc = 0.f;

        // Software-pipelined loads (one t ahead).
        float l1 = ytb[tA * NN + j];
        float l2 = ytb[(tA + 1) * NN + j];
        float yp = ypb[tA * NN + j];
        int   kk = spb[tA];

        for (int t2 = tA; t2 < tBn; t2++) {
            if (p == 0) l1sh[(t2 & 1) * 48 + j] = l1;

            int tn = min(t2 + 1, tBn - 1);
            float l1n = ytb[tn * NN + j];
            float l2n = ytb[(tn + 1) * NN + j];
            float ypn = ypb[tn * NN + j];
            int   kkn = spb[tn];

            __syncthreads();   // single barrier per t (double buffer covers WAR)
            const float* l1s = l1sh + (t2 & 1) * 48 + 12 * p;
            float u0 = 0.f, u1 = 0.f;
            if (kk == 0) {
                #pragma unroll
                for (int i = 0; i < 12; i += 2) {
                    u0 += l1s[i]     * T0[i];
                    u1 += l1s[i + 1] * T0[i + 1];
                }
            } else if (kk == 1) {
                #pragma unroll
                for (int i = 0; i < 12; i += 2) {
                    u0 += l1s[i]     * T1[i];
                    u1 += l1s[i + 1] * T1[i + 1];
                }
            } else {
                #pragma unroll
                for (int i = 0; i < 12; i += 2) {
                    u0 += l1s[i]     * T2[i];
                    u1 += l1s[i + 1] * T2[i + 1];
                }
            }
            tacc += (u0 + u1) * l2;
            if (p == 0) pacc += yp * l1;

            l1 = l1n; l2 = l2n; yp = ypn; kk = kkn;
        }
        if (c == CH - 1 && p == 0) {   // point-score term for t = T-1
            pacc += ypb[(TT - 1) * NN + j] * ytb[(TT - 1) * NN + j];
        }
        red[tid] = pacc + tacc;
        __syncthreads();
        if (tid == 0) {
            float ssum = 0.f;
            for (int q = 0; q < NTH; q++) ssum += red[q];  // fixed order -> deterministic
            g_part[b][c] = ssum;
        }
    }

    // ================= Fused combine: last block to finish does it =================
    __threadfence();                       // publish this block's results
    if (tid == 0) {
        int c = atomicAdd(&g_count, 1);
        s_last = (c == NBLK - 1);
    }
    __syncthreads();
    if (s_last) {
        __threadfence();                   // all other blocks' writes now visible
        if (tid < BB) {
            float q = 0.f;
            #pragma unroll
            for (int c2 = 0; c2 < CH; c2++) q += g_part[tid][c2];  // fixed order
            out[tid] = g_lognorm[tid] - q;
        }
        if (tid == 0) g_count = 0;         // reset for next graph replay
    }
}

extern "C" void kernel_launch(void* const* d_in, const int* in_sizes, int n_in,
                              void* d_out, int out_size)
{
    const float* y_true = (const float*)d_in[0];
    const float* y_pred = (const float*)d_in[1];
    const int*   spkseq = (const int*)d_in[2];
    const float* tr0    = (const float*)d_in[3];
    const float* tr1    = (const float*)d_in[4];
    const float* tr2    = (const float*)d_in[5];

    crf_main<<<NBLK, NTH>>>(y_true, y_pred, spkseq, tr0, tr1, tr2, (float*)d_out);
}

// round 16
// speedup vs baseline: 2.8596x; 2.8596x over previous
#include <cuda_runtime.h>

#define BB 64
#define TT 1024
#define NN 48
#define CH 8
#define SPLIT 4                    // segment chunks per batch
#define SEGB (BB * SPLIT)          // 256 segment blocks
#define NBLK (SEGB + BB * CH)      // + 512 score blocks = 768
#define NTH 128
#define NW 4                       // warps per block
#define RES (SPLIT * NW)           // 16 segment residues per batch

// Scratch (no cudaMalloc allowed)
__device__ float g_logpart[BB][SPLIT];
__device__ float g_part[BB][CH];
__device__ int   g_count = 0;      // combine ticket; reset by combiner each call

__global__ __launch_bounds__(NTH) void crf_main(
    const float* __restrict__ y_true,
    const float* __restrict__ y_pred,
    const int*   __restrict__ spk,
    const float* __restrict__ tr0,
    const float* __restrict__ tr1,
    const float* __restrict__ tr2,
    float* __restrict__ out)
{
    // Segment blocks: Esh (3x48x48, row stride 50) + list (<=1025 ints) + per-warp u[2][48].
    // Score blocks overlay the same buffer.
    __shared__ __align__(16) float sbuf[7200 + 1028 + 2 * NW * 48 + 8];
    __shared__ int   s_cnt;
    __shared__ float s_wacc[NW];
    __shared__ int   s_last;
    const int tid  = threadIdx.x;
    const int wid  = tid >> 5;
    const int lane = tid & 31;

    if (blockIdx.x < SEGB) {
        // ========== Segment solver: trans2 == 0 -> E2 == ones -> every k==2 step
        // collapses the state to (scalar) * exp(y_pred[t]). Chain splits into
        // independent segments between k==2 events. ==========
        const int b     = blockIdx.x / SPLIT;
        const int chunk = blockIdx.x - b * SPLIT;

        float* Esh   = sbuf;                   // exp(TRANS), k stride 2400, row stride 50
        int*   list  = (int*)(sbuf + 7200);    // segment start times
        float* ubase = sbuf + 7200 + 1028;     // per-warp state [NW][2][48]

        for (int idx = tid; idx < 3 * 48 * 48; idx += NTH) {
            int k  = idx / 2304;
            int rc = idx - k * 2304;
            int r  = rc / 48;
            int cc = rc - r * 48;
            const float* Tk = (k == 0) ? tr0 : (k == 1) ? tr1 : tr2;
            Esh[k * 2400 + r * 50 + cc] = __expf(Tk[rc]);
        }

        const float* ypb = y_pred + b * TT * NN;
        const int*   spb = spk + b * (TT - 1);

        // Warp 0 builds the ordered list of segment starts: t=0 plus every t
        // with k_t == 2 (i.e. spb[t-1] == 2). Ballot scan, deterministic.
        if (wid == 0) {
            int count = 1;
            if (lane == 0) list[0] = 0;
            for (int base = 1; base <= TT - 1; base += 32) {
                int  t   = base + lane;
                bool is2 = (t <= TT - 1) && (spb[t - 1] == 2);
                unsigned msk = __ballot_sync(0xffffffffu, is2);
                int pre = __popc(msk & ((1u << lane) - 1u));
                if (is2) list[count + pre] = t;
                count += __popc(msk);
            }
            if (lane == 0) s_cnt = count;
        }
        __syncthreads();
        const int count = s_cnt;

        float* up  = ubase + wid * 96;         // this warp's u[2][48]
        const int res = chunk * NW + wid;      // this warp's residue class
        const int j2  = 32 + (lane & 15);      // second output column (lanes 0..15 own it)
        float lacc = 0.f;

        for (int s = res; s < count; s += RES) {
            int t0 = list[s];
            int t1 = (s + 1 < count) ? list[s + 1] : TT;

            // u = exp(y_pred[t0]) (exact segment start state).
            up[lane] = __expf(ypb[t0 * NN + lane]);
            if (lane < 16) up[32 + lane] = __expf(ypb[t0 * NN + j2]);
            int   cur  = 0;
            float mloc = 0.f;
            __syncwarp();

            // Software-pipelined by one step (clamped, always in-bounds).
            int   t    = t0 + 1;
            int   tc   = min(t, TT - 1);
            int   kk_n = spb[tc - 1];
            float y1_n = ypb[tc * NN + lane];
            float y2_n = ypb[tc * NN + j2];

            for (; t < t1; t++) {
                const int   kk = kk_n;
                const float y1 = y1_n, y2 = y2_n;
                int tn = min(t + 1, t1 - 1); tn = min(tn, TT - 1);
                kk_n = spb[tn - 1];
                y1_n = ypb[tn * NN + lane];
                y2_n = ypb[tn * NN + j2];

                const float* U   = up + cur * 48;
                float u00 = U[0];
                float rp  = __fdividef(1.f, u00);

                float uv[48];
                #pragma unroll
                for (int q = 0; q < 12; q++) {
                    float4 f4 = *(const float4*)(U + 4 * q);   // broadcast
                    uv[4*q] = f4.x; uv[4*q+1] = f4.y; uv[4*q+2] = f4.z; uv[4*q+3] = f4.w;
                }
                const float* E = Esh + kk * 2400;
                float a0=0.f,a1=0.f,a2=0.f,a3=0.f, c0=0.f,c1=0.f,c2=0.f,c3=0.f;
                #pragma unroll
                for (int i = 0; i < 48; i += 4) {
                    a0 += uv[i]   * E[(i    ) * 50 + lane];
                    a1 += uv[i+1] * E[(i + 1) * 50 + lane];
                    a2 += uv[i+2] * E[(i + 2) * 50 + lane];
                    a3 += uv[i+3] * E[(i + 3) * 50 + lane];
                    c0 += uv[i]   * E[(i    ) * 50 + j2];
                    c1 += uv[i+1] * E[(i + 1) * 50 + j2];
                    c2 += uv[i+2] * E[(i + 2) * 50 + j2];
                    c3 += uv[i+3] * E[(i + 3) * 50 + j2];
                }
                float d1 = (a0 + a1) + (a2 + a3);
                float d2 = (c0 + c1) + (c2 + c3);
                float e1 = __expf(y1);
                float e2 = __expf(y2);
                mloc += __logf(u00);               // uniform across lanes

                float* W = up + (cur ^ 1) * 48;
                W[lane] = d1 * e1 * rp;
                if (lane < 16) W[32 + lane] = d2 * e2 * rp;
                __syncwarp();                      // publish W for next iteration
                cur ^= 1;
            }

            // Segment scalar: sum of final (renormalized) state + renorm logs.
            const float* U = up + cur * 48;
            float part = U[lane] + ((lane < 16) ? U[32 + lane] : 0.f);
            #pragma unroll
            for (int d = 16; d; d >>= 1)
                part += __shfl_xor_sync(0xffffffffu, part, d);
            lacc += mloc + __logf(part);
            __syncwarp();                          // done with up before next segment init
        }

        if (lane == 0) s_wacc[wid] = lacc;
        __syncthreads();
        if (tid == 0) {
            float ssum = 0.f;
            #pragma unroll
            for (int w = 0; w < NW; w++) ssum += s_wacc[w];   // fixed order
            g_logpart[b][chunk] = ssum;
        }
    } else {
        // ================= Score reductions: (b, chunk) blocks =================
        int idx = blockIdx.x - SEGB;
        int b   = idx / CH;
        int c   = idx - b * CH;

        float* l1sh = sbuf;        // [2][48] double buffer
        float* red  = sbuf + 96;   // NTH-wide reduction scratch

        const bool act = tid < 96;
        const int  p   = tid & 1;
        const int  j   = tid >> 1;   // 0..63; active iff j < 48

        float T0[24], T1[24], T2[24];
        if (act) {
            #pragma unroll
            for (int i = 0; i < 24; i++) {
                int rc = (24 * p + i) * NN + j;
                T0[i] = tr0[rc];
                T1[i] = tr1[rc];
                T2[i] = tr2[rc];
            }
        }

        const float* ytb = y_true + b * TT * NN;
        const float* ypb = y_pred + b * TT * NN;
        const int*   spb = spk + b * (TT - 1);

        const int LEN = (TT - 1 + CH - 1) / CH;   // 128
        int tA  = c * LEN;
        int tBn = tA + LEN; if (tBn > TT - 1) tBn = TT - 1;

        float pacc = 0.f, tacc = 0.f;

        float l1 = 0.f, l2 = 0.f, yp = 0.f;
        int   kk = spb[tA];
        if (act) {
            l1 = ytb[tA * NN + j];
            l2 = ytb[(tA + 1) * NN + j];
            yp = ypb[tA * NN + j];
        }

        for (int t2 = tA; t2 < tBn; t2++) {
            if (act && p == 0) l1sh[(t2 & 1) * 48 + j] = l1;

            int tn = min(t2 + 1, tBn - 1);
            float l1n = 0.f, l2n = 0.f, ypn = 0.f;
            int   kkn = spb[tn];
            if (act) {
                l1n = ytb[tn * NN + j];
                l2n = ytb[(tn + 1) * NN + j];
                ypn = ypb[tn * NN + j];
            }

            __syncthreads();   // single barrier per t (double buffer covers WAR)
            if (act) {
                const float* l1s = l1sh + (t2 & 1) * 48 + 24 * p;
                float u0 = 0.f, u1 = 0.f;
                if (kk == 0) {
                    #pragma unroll
                    for (int i = 0; i < 24; i += 2) {
                        u0 += l1s[i]     * T0[i];
                        u1 += l1s[i + 1] * T0[i + 1];
                    }
                } else if (kk == 1) {
                    #pragma unroll
                    for (int i = 0; i < 24; i += 2) {
                        u0 += l1s[i]     * T1[i];
                        u1 += l1s[i + 1] * T1[i + 1];
                    }
                } else {
                    #pragma unroll
                    for (int i = 0; i < 24; i += 2) {
                        u0 += l1s[i]     * T2[i];
                        u1 += l1s[i + 1] * T2[i + 1];
                    }
                }
                tacc += (u0 + u1) * l2;
                if (p == 0) pacc += yp * l1;
            }
            l1 = l1n; l2 = l2n; yp = ypn; kk = kkn;
        }
        if (act && c == CH - 1 && p == 0) {   // point-score term for t = T-1
            pacc += ypb[(TT - 1) * NN + j] * ytb[(TT - 1) * NN + j];
        }
        red[tid] = act ? (pacc + tacc) : 0.f;
        __syncthreads();
        if (tid == 0) {
            float ssum = 0.f;
            for (int q = 0; q < 96; q++) ssum += red[q];  // fixed order -> deterministic
            g_part[b][c] = ssum;
        }
    }

    // ================= Fused combine: last block to finish does it =================
    __threadfence();                       // publish this block's results
    if (tid == 0) {
        int c = atomicAdd(&g_count, 1);
        s_last = (c == NBLK - 1);
    }
    __syncthreads();
    if (s_last) {
        __threadfence();                   // all other blocks' writes now visible
        if (tid < BB) {
            float ln = 0.f;
            #pragma unroll
            for (int c2 = 0; c2 < SPLIT; c2++) ln += g_logpart[tid][c2];  // fixed order
            float q = 0.f;
            #pragma unroll
            for (int c2 = 0; c2 < CH; c2++) q += g_part[tid][c2];         // fixed order
            out[tid] = ln - q;
        }
        if (tid == 0) g_count = 0;         // reset for next graph replay
    }
}

extern "C" void kernel_launch(void* const* d_in, const int* in_sizes, int n_in,
                              void* d_out, int out_size)
{
    const float* y_true = (const float*)d_in[0];
    const float* y_pred = (const float*)d_in[1];
    const int*   spkseq = (const int*)d_in[2];
    const float* tr0    = (const float*)d_in[3];
    const float* tr1    = (const float*)d_in[4];
    const float* tr2    = (const float*)d_in[5];

    crf_main<<<NBLK, NTH>>>(y_true, y_pred, spkseq, tr0, tr1, tr2, (float*)d_out);
}

// round 17
// speedup vs baseline: 3.6628x; 1.2809x over previous
#include <cuda_runtime.h>

#define BB 64
#define TT 1024
#define NN 48
#define CH 8
#define SPLIT 4                    // segment chunks per batch
#define SEGB (BB * SPLIT)          // 256 segment blocks
#define NBLK (SEGB + BB * CH)      // + 512 score blocks = 768
#define NTH 128
#define NW 4                       // warps per block
#define RES (SPLIT * NW)           // 16 segment residues per batch

#define ECOL 52                    // E column stride (floats): 13 chunks, odd -> conflict-free
#define EKS  (NN * ECOL)           // 2496 floats per matrix
#define LISTOFF (3 * EKS)          // 7488
#define UOFF (LISTOFF + 1028)      // 8516

// Scratch (no cudaMalloc allowed)
__device__ float g_logpart[BB][SPLIT];
__device__ float g_part[BB][CH];
__device__ int   g_count = 0;      // combine ticket; reset by combiner each call

__global__ __launch_bounds__(NTH) void crf_main(
    const float* __restrict__ y_true,
    const float* __restrict__ y_pred,
    const int*   __restrict__ spk,
    const float* __restrict__ tr0,
    const float* __restrict__ tr1,
    const float* __restrict__ tr2,
    float* __restrict__ out)
{
    // Segment blocks: Esh (3 mats, COLUMN-major, col stride 52) + list + per-warp u[2][48].
    // Score blocks overlay the same buffer.
    __shared__ __align__(16) float sbuf[UOFF + 2 * NW * 48 + 8];
    __shared__ int   s_cnt;
    __shared__ float s_wacc[NW];
    __shared__ int   s_last;
    const int tid  = threadIdx.x;
    const int wid  = tid >> 5;
    const int lane = tid & 31;

    if (blockIdx.x < SEGB) {
        // ========== Segment solver: trans2 == 0 -> every k==2 step collapses the
        // state to (scalar) * exp(y_pred[t]); chain splits into independent segments.
        const int b     = blockIdx.x / SPLIT;
        const int chunk = blockIdx.x - b * SPLIT;

        float* Esh   = sbuf;                   // exp(TRANS)^T: [k][col][row], row contiguous
        int*   list  = (int*)(sbuf + LISTOFF); // segment start times
        float* ubase = sbuf + UOFF;            // per-warp state [NW][2][48]

        for (int idx = tid; idx < 3 * NN * NN; idx += NTH) {
            int k  = idx / 2304;
            int rc = idx - k * 2304;
            int i  = rc / 48;                  // row of T
            int cj = rc - i * 48;              // col of T
            const float* Tk = (k == 0) ? tr0 : (k == 1) ? tr1 : tr2;
            Esh[k * EKS + cj * ECOL + i] = __expf(Tk[rc]);
        }

        const float* ypb = y_pred + b * TT * NN;
        const int*   spb = spk + b * (TT - 1);

        // Warp 0 builds the ordered list of segment starts (ballot scan).
        if (wid == 0) {
            int count = 1;
            if (lane == 0) list[0] = 0;
            for (int base = 1; base <= TT - 1; base += 32) {
                int  t   = base + lane;
                bool is2 = (t <= TT - 1) && (spb[t - 1] == 2);
                unsigned msk = __ballot_sync(0xffffffffu, is2);
                int pre = __popc(msk & ((1u << lane) - 1u));
                if (is2) list[count + pre] = t;
                count += __popc(msk);
            }
            if (lane == 0) s_cnt = count;
        }
        __syncthreads();
        const int count = s_cnt;

        float* up  = ubase + wid * 96;         // this warp's u[2][48]
        const int res = chunk * NW + wid;      // this warp's residue class
        const int j2  = 32 + (lane & 15);      // second output column (lanes 0..15 own it)
        float lacc = 0.f;

        for (int s = res; s < count; s += RES) {
            int t0 = list[s];
            int t1 = (s + 1 < count) ? list[s + 1] : TT;

            up[lane] = __expf(ypb[t0 * NN + lane]);
            if (lane < 16) up[32 + lane] = __expf(ypb[t0 * NN + j2]);
            int   cur  = 0;
            float mloc = 0.f;
            __syncwarp();

            // Software-pipelined by one step (clamped, always in-bounds).
            int   t    = t0 + 1;
            int   tc   = min(t, TT - 1);
            int   kk_n = spb[tc - 1];
            float y1_n = ypb[tc * NN + lane];
            float y2_n = ypb[tc * NN + j2];

            for (; t < t1; t++) {
                const int   kk = kk_n;
                const float y1 = y1_n, y2 = y2_n;
                int tn = min(t + 1, t1 - 1); tn = min(tn, TT - 1);
                kk_n = spb[tn - 1];
                y1_n = ypb[tn * NN + lane];
                y2_n = ypb[tn * NN + j2];

                const float* U   = up + cur * 48;
                float u00 = U[0];
                float rp  = __fdividef(1.f, u00);

                // Two contiguous E columns per lane: 24 LDS.128 total (+12 broadcast u).
                const float* Ea = Esh + kk * EKS + lane * ECOL;
                const float* Eb = Esh + kk * EKS + j2 * ECOL;

                float a0=0.f,a1=0.f,a2=0.f,a3=0.f, c0=0.f,c1=0.f,c2=0.f,c3=0.f;
                #pragma unroll
                for (int q = 0; q < 12; q++) {
                    float4 u4 = *(const float4*)(U  + 4 * q);   // broadcast
                    float4 e4 = *(const float4*)(Ea + 4 * q);
                    float4 f4 = *(const float4*)(Eb + 4 * q);
                    a0 += u4.x * e4.x; a1 += u4.y * e4.y;
                    a2 += u4.z * e4.z; a3 += u4.w * e4.w;
                    c0 += u4.x * f4.x; c1 += u4.y * f4.y;
                    c2 += u4.z * f4.z; c3 += u4.w * f4.w;
                }
                float d1 = (a0 + a1) + (a2 + a3);
                float d2 = (c0 + c1) + (c2 + c3);
                float e1 = __expf(y1);
                float e2 = __expf(y2);
                mloc += __logf(u00);               // uniform across lanes

                float* W = up + (cur ^ 1) * 48;
                W[lane] = d1 * e1 * rp;
                if (lane < 16) W[32 + lane] = d2 * e2 * rp;
                __syncwarp();                      // publish W for next iteration
                cur ^= 1;
            }

            // Segment scalar: sum of final (renormalized) state + renorm logs.
            const float* U = up + cur * 48;
            float part = U[lane] + ((lane < 16) ? U[32 + lane] : 0.f);
            #pragma unroll
            for (int d = 16; d; d >>= 1)
                part += __shfl_xor_sync(0xffffffffu, part, d);
            lacc += mloc + __logf(part);
            __syncwarp();                          // done with up before next segment init
        }

        if (lane == 0) s_wacc[wid] = lacc;
        __syncthreads();
        if (tid == 0) {
            float ssum = 0.f;
            #pragma unroll
            for (int w = 0; w < NW; w++) ssum += s_wacc[w];   // fixed order
            g_logpart[b][chunk] = ssum;
        }
    } else {
        // ================= Score reductions: (b, chunk) blocks =================
        int idx = blockIdx.x - SEGB;
        int b   = idx / CH;
        int c   = idx - b * CH;

        float* l1sh = sbuf;        // [2][48] double buffer (parity advances on non-skip t)
        float* red  = sbuf + 96;   // NTH-wide reduction scratch

        const bool act = tid < 96;
        const int  p   = tid & 1;
        const int  j   = tid >> 1;

        // T2 == 0 (problem invariant) -> k==2 contributes nothing: only T0/T1 needed.
        float T0[24], T1[24];
        if (act) {
            #pragma unroll
            for (int i = 0; i < 24; i++) {
                int rc = (24 * p + i) * NN + j;
                T0[i] = tr0[rc];
                T1[i] = tr1[rc];
            }
        }

        const float* ytb = y_true + b * TT * NN;
        const float* ypb = y_pred + b * TT * NN;
        const int*   spb = spk + b * (TT - 1);

        const int LEN = (TT - 1 + CH - 1) / CH;   // 128
        int tA  = c * LEN;
        int tBn = tA + LEN; if (tBn > TT - 1) tBn = TT - 1;

        float pacc = 0.f, tacc = 0.f;

        float l1 = 0.f, l2 = 0.f, yp = 0.f;
        int   kk = spb[tA];
        if (act) {
            l1 = ytb[tA * NN + j];
            l2 = ytb[(tA + 1) * NN + j];
            yp = ypb[tA * NN + j];
        }

        int par = 0;
        for (int t2 = tA; t2 < tBn; t2++) {
            const bool skip = (kk == 2);          // block-uniform
            if (!skip && act && p == 0) l1sh[par * 48 + j] = l1;

            int tn = min(t2 + 1, tBn - 1);
            float l1n = 0.f, l2n = 0.f, ypn = 0.f;
            int   kkn = spb[tn];
            if (act) {
                l1n = ytb[tn * NN + j];
                l2n = ytb[(tn + 1) * NN + j];
                ypn = ypb[tn * NN + j];
            }

            if (!skip) {
                __syncthreads();                  // uniform (skip is block-uniform)
                if (act) {
                    const float* l1s = l1sh + par * 48 + 24 * p;
                    float u0 = 0.f, u1 = 0.f;
                    if (kk == 0) {
                        #pragma unroll
                        for (int i = 0; i < 24; i += 2) {
                            u0 += l1s[i]     * T0[i];
                            u1 += l1s[i + 1] * T0[i + 1];
                        }
                    } else {
                        #pragma unroll
                        for (int i = 0; i < 24; i += 2) {
                            u0 += l1s[i]     * T1[i];
                            u1 += l1s[i + 1] * T1[i + 1];
                        }
                    }
                    tacc += (u0 + u1) * l2;
                }
                par ^= 1;
            }
            if (act && p == 0) pacc += yp * l1;

            l1 = l1n; l2 = l2n; yp = ypn; kk = kkn;
        }
        if (act && c == CH - 1 && p == 0) {   // point-score term for t = T-1
            pacc += ypb[(TT - 1) * NN + j] * ytb[(TT - 1) * NN + j];
        }
        red[tid] = act ? (pacc + tacc) : 0.f;
        __syncthreads();
        if (tid == 0) {
            float ssum = 0.f;
            for (int q = 0; q < 96; q++) ssum += red[q];  // fixed order -> deterministic
            g_part[b][c] = ssum;
        }
    }

    // ================= Fused combine: last block to finish does it =================
    __threadfence();                       // publish this block's results
    if (tid == 0) {
        int c = atomicAdd(&g_count, 1);
        s_last = (c == NBLK - 1);
    }
    __syncthreads();
    if (s_last) {
        __threadfence();                   // all other blocks' writes now visible
        if (tid < BB) {
            float ln = 0.f;
            #pragma unroll
            for (int c2 = 0; c2 < SPLIT; c2++) ln += g_logpart[tid][c2];  // fixed order
            float q = 0.f;
            #pragma unroll
            for (int c2 = 0; c2 < CH; c2++) q += g_part[tid][c2];         // fixed order
            out[tid] = ln - q;
        }
        if (tid == 0) g_count = 0;         // reset for next graph replay
    }
}

extern "C" void kernel_launch(void* const* d_in, const int* in_sizes, int n_in,
                              void* d_out, int out_size)
{
    const float* y_true = (const float*)d_in[0];
    const float* y_pred = (const float*)d_in[1];
    const int*   spkseq = (const int*)d_in[2];
    const float* tr0    = (const float*)d_in[3];
    const float* tr1    = (const float*)d_in[4];
    const float* tr2    = (const float*)d_in[5];

    crf_main<<<NBLK, NTH>>>(y_true, y_pred, spkseq, tr0, tr1, tr2, (float*)d_out);
}